// round 12
// baseline (speedup 1.0000x reference)
#include <cuda_runtime.h>
#include <cstdint>

#define T_STEPS 512
#define N_SIM   32
#define N_PROD  116
#define N_TILES (T_STEPS * 32)
#define N_TICKS (T_STEPS + 4)

__device__ __align__(8) float g_w3t[400 * 120 + 128]; // conv3 weights [k][o] (padded)
__device__ float g_fw1t[120 * 84];                    // fc1 weights [k][g]
__device__ float g_fw2t[84 * 10];                     // fc2 weights [k][o]
__device__ float g_drive1[(size_t)N_TILES * 4704];    // conv1 drive [t][b][4704]
__device__ int   g_ready[N_TILES];

// ---------------- threefry2x32 (JAX), 20 rounds ----------------
__device__ __forceinline__ void threefry(unsigned k0, unsigned k1,
                                         unsigned x0, unsigned x1,
                                         unsigned &o0, unsigned &o1)
{
    unsigned k2 = k0 ^ k1 ^ 0x1BD11BDAu;
    x0 += k0; x1 += k1;
#define TF_R(r) { x0 += x1; x1 = __funnelshift_l(x1, x1, (r)); x1 ^= x0; }
    TF_R(13) TF_R(15) TF_R(26) TF_R(6)
    x0 += k1; x1 += k2 + 1u;
    TF_R(17) TF_R(29) TF_R(16) TF_R(24)
    x0 += k2; x1 += k0 + 2u;
    TF_R(13) TF_R(15) TF_R(26) TF_R(6)
    x0 += k0; x1 += k1 + 3u;
    TF_R(17) TF_R(29) TF_R(16) TF_R(24)
    x0 += k1; x1 += k2 + 4u;
    TF_R(13) TF_R(15) TF_R(26) TF_R(6)
    x0 += k2; x1 += k0 + 5u;
#undef TF_R
    o0 = x0; o1 = x1;
}

__global__ void __launch_bounds__(1024) reset_kernel()
{
    int i = blockIdx.x * 1024 + threadIdx.x;
    if (i < N_TILES) g_ready[i] = 0;
}

// transpose conv3/fc1/fc2 weights
__global__ void __launch_bounds__(256) prep_kernel(const float* __restrict__ w3,
                                                   const float* __restrict__ fw1,
                                                   const float* __restrict__ fw2)
{
    int i = blockIdx.x * 256 + threadIdx.x;
    if (i < 48000) {
        int k = i / 120, o = i % 120;
        g_w3t[i] = w3[o * 400 + k];
    } else if (i < 58080) {
        int j = i - 48000;                       // j = k*84 + g
        int k = j / 84, g = j % 84;
        g_fw1t[j] = fw1[g * 120 + k];
    } else if (i < 58920) {
        int j = i - 58080;                       // j = k*10 + o
        int k = j / 10, o = j % 10;
        g_fw2t[j] = fw2[o * 84 + k];
    }
}

// ---------------- shared memory map (float offsets) ----------------
#define SM_DRV    0        // 9408 = 2 x 4704 drive double buffer
#define SM_SKB    9408     // 2352 = 2 x 1176
#define SM_M12A   11760    // 9408 (layer1 membranes, float2)
#define SM_M12C   21168    // 3200 (conv2-out membranes, float2)
#define SM_SKD    24368    // 800 = 2 x 400 (pooled layer4 spikes, dense)
#define SM_SKE    25168    // 240 = 2 x 120
#define SM_SKF    25408    // 168 = 2 x 84
#define SM_W2     25576    // 2400
#define SM_FW1T   27976    // 10080
#define SM_FW2T   38056    // 840
#define SM_TOTAL  38896
#define SMEM_BYTES (SM_TOTAL * 4)
#define SM_ZBEG   SM_M12A
#define SM_ZEND   SM_W2
// producer view of the same smem
#define PM_XF     0
#define PM_W1     1024

__global__ void __launch_bounds__(1024, 1)
fused_kernel(const float* __restrict__ image, const float* __restrict__ w1,
             const float* __restrict__ w2, float* __restrict__ out)
{
    extern __shared__ float sm[];
    const int tid  = threadIdx.x;
    const int lane = tid & 31;

    if (blockIdx.x >= N_SIM) {
        // ================= PRODUCER: RNG + conv1 for tiles (t,b) =================
        const int p = blockIdx.x - N_SIM;
        if (tid < 150) sm[PM_W1 + tid] = w1[tid];
        __syncthreads();
        const int c1_c  = tid / 112;           // conv1: tid<672
        const int c1_r  = tid % 112;
        const int c1_oy = c1_r >> 2;
        const int c1_x0 = (c1_r & 3) * 7;

        for (int idx = p; idx < N_TILES; idx += N_PROD) {
            int t = idx >> 5, b = idx & 31;
            unsigned k0, k1;
            threefry(0u, 1u, 0u, (unsigned)t, k0, k1);
            unsigned o0, o1;
            threefry(k0, k1, 0u, (unsigned)(b * 1024 + tid), o0, o1);
            unsigned bits = o0 ^ o1;
            float u = __uint_as_float(0x3f800000u | (bits >> 9)) - 1.0f;
            float r = __ldg(image + b * 1024 + tid) * 0.1953125f;
            sm[PM_XF + tid] = (r > u) ? 1.f : 0.f;
            __syncthreads();

            if (tid < 672) {
                const float* wr = sm + PM_W1 + c1_c * 25;
                float acc[7];
#pragma unroll
                for (int o = 0; o < 7; o++) acc[o] = 0.f;
#pragma unroll
                for (int ky = 0; ky < 5; ky++) {
                    const float* row = sm + PM_XF + (c1_oy + ky) * 32 + c1_x0;
                    float in[11];
#pragma unroll
                    for (int q = 0; q < 11; q++) in[q] = row[q];
#pragma unroll
                    for (int kx = 0; kx < 5; kx++) {
                        float wv = wr[ky * 5 + kx];
#pragma unroll
                        for (int o = 0; o < 7; o++)
                            acc[o] = fmaf(wv, in[kx + o], acc[o]);
                    }
                }
                float* outp = g_drive1 + (size_t)idx * 4704
                            + c1_c * 784 + c1_oy * 28 + c1_x0;
#pragma unroll
                for (int o = 0; o < 7; o++) outp[o] = acc[o];
            }
            __syncthreads();
            if (tid == 0) {
                __threadfence();
                ((volatile int*)g_ready)[idx] = 1;
            }
        }
        return;
    }

    // ================= SIM CTA: 4-deep layer pipeline =================
    const int b = blockIdx.x;

    for (int i = tid; i < 2400;  i += 1024) sm[SM_W2   + i] = w2[i];
    for (int i = tid; i < 10080; i += 1024) sm[SM_FW1T + i] = g_fw1t[i];
    for (int i = tid; i < 840;   i += 1024) sm[SM_FW2T + i] = g_fw2t[i];
    for (int i = tid; i < (SM_ZEND - SM_ZBEG); i += 1024) sm[SM_ZBEG + i] = 0.0f;
    if (tid == 0) {
        while (((volatile int*)g_ready)[b] == 0) __nanosleep(64);
    }
    __syncthreads();
    __threadfence();
    {   // preload drive for t=0 into slot 0
        const float4* src = (const float4*)(g_drive1 + (size_t)b * 4704);
        float4* dst = (float4*)(sm + SM_DRV);
        for (int i = tid; i < 1176; i += 1024) dst[i] = src[i];
    }
    __syncthreads();

    // ---- per-stage register state ----
    // S1 (lif1/lif2):
    float pm1[7], pm2[7];
#pragma unroll
    for (int i = 0; i < 7; i++) { pm1[i] = 0.f; pm2[i] = 0.f; }
    // S2' (lif4 pooled):
    float qm1 = 0.f, qm2 = 0.f;
    // S3' (lif5, 2 outputs):
    float em1[2] = {0.f, 0.f}, em2[2] = {0.f, 0.f};
    // S4' D (lif6):
    float fm1 = 0.f, fm2 = 0.f;
    // S4' E (lif7 + acc):
    float gm1 = 0.f, gm2 = 0.f, eacc = 0.f;

#pragma unroll 1
    for (int n = 0; n < N_TICKS; n++) {
        const int ws = n & 1;              // write slot
        const int rs = ws ^ 1;             // read slot (written last tick)

        if (tid < 448) {
            // ---- S2': fused conv2 + lif3 + pool + lif4, t = n-1 ----
            if (n >= 1 && n <= T_STEPS && tid < 400) {
                const int oc = tid & 15, blk = tid >> 4;
                const int py = blk / 5, px = blk % 5;
                const float* skb = sm + SM_SKB + rs * 1176;
                const float* wb  = sm + SM_W2 + oc * 150;
                float a00 = 0.f, a01 = 0.f, a10 = 0.f, a11 = 0.f;
#pragma unroll
                for (int ic = 0; ic < 6; ic++) {
                    const float* ib = skb + ic * 196 + 2 * py * 14 + 2 * px;
                    const float* wr = wb + ic * 25;
                    float in[6][6];
#pragma unroll
                    for (int r = 0; r < 6; r++) {
                        const float* rp = ib + r * 14;
                        float2 x0 = *(const float2*)rp;
                        float2 x1 = *(const float2*)(rp + 2);
                        float2 x2 = *(const float2*)(rp + 4);
                        in[r][0] = x0.x; in[r][1] = x0.y; in[r][2] = x1.x;
                        in[r][3] = x1.y; in[r][4] = x2.x; in[r][5] = x2.y;
                    }
#pragma unroll
                    for (int ky = 0; ky < 5; ky++)
#pragma unroll
                        for (int kx = 0; kx < 5; kx++) {
                            float wv = wr[ky * 5 + kx];
                            a00 = fmaf(wv, in[ky][kx],         a00);
                            a01 = fmaf(wv, in[ky][kx + 1],     a01);
                            a10 = fmaf(wv, in[ky + 1][kx],     a10);
                            a11 = fmaf(wv, in[ky + 1][kx + 1], a11);
                        }
                }
                float dr[4] = {a00, a01, a10, a11};
                float psum = 0.f;
                int ob = oc * 100 + 2 * py * 10 + 2 * px;
#pragma unroll
                for (int q = 0; q < 4; q++) {
                    int o = ob + (q >> 1) * 10 + (q & 1);
                    float2 m = *(float2*)(sm + SM_M12C + 2 * o);
                    float oms = (m.y > 0.3f) ? 0.f : 1.f;
                    float n1 = m.x * 0.25f * oms + dr[q];
                    float n2 = m.y * 0.25f * oms + 0.5f * n1;
                    *(float2*)(sm + SM_M12C + 2 * o) = make_float2(n1, n2);
                    psum += (n2 > 0.3f) ? 1.f : 0.f;
                }
                float d   = 0.25f * psum;
                float oms = (qm2 > 0.3f) ? 0.f : 1.f;
                float n1  = qm1 * 0.25f * oms + d;
                float n2  = qm2 * 0.25f * oms + 0.5f * n1;
                qm1 = n1; qm2 = n2;
                sm[SM_SKD + ws * 400 + oc * 25 + blk] = (n2 > 0.3f) ? 1.f : 0.f;
            }
        } else if (tid < 640) {
            // ---- S1: lif1 + pool + lif2, t = n ----
            const int local = tid - 448;
            if (n <= T_STEPS - 1 && local < 168) {
                const int c = local / 28, rem = local % 28;
                const int by = rem >> 1, h = rem & 1;
                const int rowbase = c * 784 + 2 * by * 28 + 14 * h;
                const float* dp = sm + SM_DRV + ws * 4704 + rowbase;
                float* skbw = sm + SM_SKB + ws * 1176 + c * 196 + by * 14 + 7 * h;
#pragma unroll
                for (int p = 0; p < 7; p++) {
                    float2 d0 = *(const float2*)(dp + 2 * p);
                    float2 d1 = *(const float2*)(dp + 28 + 2 * p);
                    int o0 = rowbase + 2 * p;
                    float4 m0 = *(float4*)(sm + SM_M12A + 2 * o0);        // row0 pair
                    float4 m1 = *(float4*)(sm + SM_M12A + 2 * (o0 + 28)); // row1 pair
                    float ps = 0.f;
                    // row0 col0
                    float oms = (m0.y > 0.3f) ? 0.f : 1.f;
                    float n1 = m0.x * 0.25f * oms + d0.x;
                    float n2 = m0.y * 0.25f * oms + 0.5f * n1;
                    m0.x = n1; m0.y = n2; ps += (n2 > 0.3f) ? 1.f : 0.f;
                    // row0 col1
                    oms = (m0.w > 0.3f) ? 0.f : 1.f;
                    n1 = m0.z * 0.25f * oms + d0.y;
                    n2 = m0.w * 0.25f * oms + 0.5f * n1;
                    m0.z = n1; m0.w = n2; ps += (n2 > 0.3f) ? 1.f : 0.f;
                    // row1 col0
                    oms = (m1.y > 0.3f) ? 0.f : 1.f;
                    n1 = m1.x * 0.25f * oms + d1.x;
                    n2 = m1.y * 0.25f * oms + 0.5f * n1;
                    m1.x = n1; m1.y = n2; ps += (n2 > 0.3f) ? 1.f : 0.f;
                    // row1 col1
                    oms = (m1.w > 0.3f) ? 0.f : 1.f;
                    n1 = m1.z * 0.25f * oms + d1.y;
                    n2 = m1.w * 0.25f * oms + 0.5f * n1;
                    m1.z = n1; m1.w = n2; ps += (n2 > 0.3f) ? 1.f : 0.f;
                    *(float4*)(sm + SM_M12A + 2 * o0) = m0;
                    *(float4*)(sm + SM_M12A + 2 * (o0 + 28)) = m1;
                    // pooled LIF
                    float d = 0.25f * ps;
                    float omsp = (pm2[p] > 0.3f) ? 0.f : 1.f;
                    float p1 = pm1[p] * 0.25f * omsp + d;
                    float p2 = pm2[p] * 0.25f * omsp + 0.5f * p1;
                    pm1[p] = p1; pm2[p] = p2;
                    skbw[p] = (p2 > 0.3f) ? 1.f : 0.f;
                }
            }
        } else if (tid < 768) {
            // ---- S3': dense conv3 + lif5, t = n-2 ----
            const int local = tid - 640;
            if (n >= 2 && n <= T_STEPS + 1) {
                const int o2 = local >> 1, par = local & 1;
                const float* skd = sm + SM_SKD + rs * 400;
                float acc0 = 0.f, acc1 = 0.f;
#pragma unroll 4
                for (int k = par; k < 400; k += 2) {
                    float s = skd[k];
                    float2 w = *(const float2*)(g_w3t + k * 120 + 2 * o2);
                    acc0 = fmaf(s, w.x, acc0);
                    acc1 = fmaf(s, w.y, acc1);
                }
                float b0 = __shfl_xor_sync(0xffffffffu, acc0, 1);
                float b1 = __shfl_xor_sync(0xffffffffu, acc1, 1);
                if (par == 0 && o2 < 60) {
                    float t0 = acc0 + b0, t1 = acc1 + b1;
                    float oms = (em2[0] > 0.3f) ? 0.f : 1.f;
                    float n1 = em1[0] * 0.25f * oms + t0;
                    float n2 = em2[0] * 0.25f * oms + 0.5f * n1;
                    em1[0] = n1; em2[0] = n2;
                    sm[SM_SKE + ws * 120 + 2 * o2] = (n2 > 0.3f) ? 1.f : 0.f;
                    oms = (em2[1] > 0.3f) ? 0.f : 1.f;
                    n1 = em1[1] * 0.25f * oms + t1;
                    n2 = em2[1] * 0.25f * oms + 0.5f * n1;
                    em1[1] = n1; em2[1] = n2;
                    sm[SM_SKE + ws * 120 + 2 * o2 + 1] = (n2 > 0.3f) ? 1.f : 0.f;
                }
            }
        } else {
            // ---- S4': fc1 (t=n-3) | fc2+acc (t=n-4) | drive prefetch (t=n+1) ----
            const int local = tid - 768;
            if (local < 84) {
                if (n >= 3 && n <= T_STEPS + 2) {
                    const float* ske = sm + SM_SKE + rs * 120;
                    float s = 0.f;
#pragma unroll 4
                    for (int k = 0; k < 120; k++)
                        s = fmaf(sm[SM_FW1T + k * 84 + local], ske[k], s);
                    float oms = (fm2 > 0.3f) ? 0.f : 1.f;
                    float n1 = fm1 * 0.25f * oms + s;
                    float n2 = fm2 * 0.25f * oms + 0.5f * n1;
                    fm1 = n1; fm2 = n2;
                    sm[SM_SKF + ws * 84 + local] = (n2 > 0.3f) ? 1.f : 0.f;
                }
            } else if (local < 94) {
                if (n >= 4 && n <= T_STEPS + 3) {
                    const int o = local - 84;
                    const float* skf = sm + SM_SKF + rs * 84;
                    float s = 0.f;
#pragma unroll 4
                    for (int k = 0; k < 84; k++)
                        s = fmaf(sm[SM_FW2T + k * 10 + o], skf[k], s);
                    float oms = (gm2 > 0.3f) ? 0.f : 1.f;
                    float n1 = gm1 * 0.25f * oms + s;
                    float n2 = gm2 * 0.25f * oms + 0.5f * n1;
                    gm1 = n1; gm2 = n2;
                    eacc += (n2 > 0.3f) ? 1.f : 0.f;
                }
            } else if (local >= 96) {
                if (n + 1 <= T_STEPS - 1) {
                    const int idx = (n + 1) * 32 + b;
                    if (lane == 0) {
                        while (((volatile int*)g_ready)[idx] == 0) __nanosleep(64);
                    }
                    __syncwarp();
                    __threadfence();
                    const float4* src = (const float4*)(g_drive1 + (size_t)idx * 4704);
                    float4* dst = (float4*)(sm + SM_DRV + ((n + 1) & 1) * 4704);
                    for (int i = local - 96; i < 1176; i += 160) dst[i] = src[i];
                }
            }
        }
        __syncthreads();
    }

    {   // output from E threads
        const int local = tid - 768;
        if (tid >= 768 && local >= 84 && local < 94)
            out[b * 10 + (local - 84)] = eacc * (1.0f / 512.0f);
    }
}

extern "C" void kernel_launch(void* const* d_in, const int* in_sizes, int n_in,
                              void* d_out, int out_size)
{
    const float* image = (const float*)d_in[0];
    const float* w1    = (const float*)d_in[1];
    const float* w2    = (const float*)d_in[2];
    const float* w3    = (const float*)d_in[3];
    const float* fw1   = (const float*)d_in[4];
    const float* fw2   = (const float*)d_in[5];
    float* out = (float*)d_out;

    reset_kernel<<<(N_TILES + 1023) / 1024, 1024>>>();
    prep_kernel<<<(58920 + 255) / 256, 256>>>(w3, fw1, fw2);
    cudaFuncSetAttribute(fused_kernel, cudaFuncAttributeMaxDynamicSharedMemorySize, SMEM_BYTES);
    fused_kernel<<<N_SIM + N_PROD, 1024, SMEM_BYTES>>>(image, w1, w2, out);
}

// round 13
// speedup vs baseline: 2.0563x; 2.0563x over previous
#include <cuda_runtime.h>
#include <cstdint>

#define T_STEPS 512
#define N_SIM   32
#define N_PROD  116
#define N_TILES (T_STEPS * 32)

__device__ __align__(8) float g_w3t[400 * 120];       // conv3 weights [k][o]
__device__ float g_drive1[(size_t)N_TILES * 4704];    // conv1 drive [t][b][4704]
__device__ int   g_ready[N_TILES];

// ---------------- threefry2x32 (JAX), 20 rounds ----------------
__device__ __forceinline__ void threefry(unsigned k0, unsigned k1,
                                         unsigned x0, unsigned x1,
                                         unsigned &o0, unsigned &o1)
{
    unsigned k2 = k0 ^ k1 ^ 0x1BD11BDAu;
    x0 += k0; x1 += k1;
#define TF_R(r) { x0 += x1; x1 = __funnelshift_l(x1, x1, (r)); x1 ^= x0; }
    TF_R(13) TF_R(15) TF_R(26) TF_R(6)
    x0 += k1; x1 += k2 + 1u;
    TF_R(17) TF_R(29) TF_R(16) TF_R(24)
    x0 += k2; x1 += k0 + 2u;
    TF_R(13) TF_R(15) TF_R(26) TF_R(6)
    x0 += k0; x1 += k1 + 3u;
    TF_R(17) TF_R(29) TF_R(16) TF_R(24)
    x0 += k1; x1 += k2 + 4u;
    TF_R(13) TF_R(15) TF_R(26) TF_R(6)
    x0 += k2; x1 += k0 + 5u;
#undef TF_R
    o0 = x0; o1 = x1;
}

__global__ void __launch_bounds__(1024) reset_kernel()
{
    int i = blockIdx.x * 1024 + threadIdx.x;
    if (i < N_TILES) g_ready[i] = 0;
}

__global__ void __launch_bounds__(256) w3t_kernel(const float* __restrict__ w3)
{
    int i = blockIdx.x * 256 + threadIdx.x;   // 48000
    if (i < 48000) {
        int k = i / 120, o = i % 120;
        g_w3t[i] = w3[o * 400 + k];
    }
}

typedef unsigned long long u64;
__device__ __forceinline__ void fma2(u64 &acc, u64 w, u64 p)
{
    asm("fma.rn.f32x2 %0, %1, %2, %3;" : "=l"(acc) : "l"(w), "l"(p), "l"(acc));
}
__device__ __forceinline__ void add2(u64 &acc, u64 p)
{
    asm("add.rn.f32x2 %0, %1, %2;" : "=l"(acc) : "l"(p), "l"(acc));
}
__device__ __forceinline__ float2 u2f(u64 v)
{
    float2 r;
    asm("mov.b64 {%0, %1}, %2;" : "=f"(r.x), "=f"(r.y) : "l"(v));
    return r;
}

// ---------------- shared memory map (float offsets, 8B-aligned bases) ------
#define SM_DRV    0        // 9408 = 2 x 4704 drive double buffer
#define SM_SKB    9408     // 1176
#define SM_SKBO   10584    // 1176  SKB shifted by +1 within each 14-row
#define SM_M12A   11760    // 9408
#define SM_M12C   21168    // 3200
#define SM_PARTB  24368    // 9600 = ic(6) x oc(16) x 10 x 10
#define SM_PARTC  33968    // 840 = 7 x 120
#define SM_SKE    34808    // 120
#define SM_M12F   34928    // 168
#define SM_SKF    35096    // 84
#define SM_M12G   35180    // 20
#define SM_ACC    35200    // 10
#define SM_WCNT   35210    // 13 ints
#define SM_LIST   35224    // 416 ints
#define SM_W2D    35640    // 4800 (w2 duplicated pairs)
#define SM_FW1    40440    // 10080
#define SM_FW2    50520    // 840
#define SM_TOTAL  51360
#define SMEM_BYTES (SM_TOTAL * 4)
#define SM_ZBEG   SM_SKB
#define SM_ZEND   SM_W2D
// producer view of the same smem
#define PM_XF     0
#define PM_W1     1024

__global__ void __launch_bounds__(1024, 1)
fused_kernel(const float* __restrict__ image, const float* __restrict__ w1,
             const float* __restrict__ w2, const float* __restrict__ fw1,
             const float* __restrict__ fw2, float* __restrict__ out)
{
    extern __shared__ float sm[];
    const int tid  = threadIdx.x;
    const int lane = tid & 31;
    const int wrp  = tid >> 5;

    if (blockIdx.x >= N_SIM) {
        // ================= PRODUCER: RNG + conv1 for tiles (t,b) =================
        const int p = blockIdx.x - N_SIM;
        if (tid < 150) sm[PM_W1 + tid] = w1[tid];
        __syncthreads();
        const int c1_c  = tid / 112;           // conv1: tid<672
        const int c1_r  = tid % 112;
        const int c1_oy = c1_r >> 2;
        const int c1_x0 = (c1_r & 3) * 7;

        for (int idx = p; idx < N_TILES; idx += N_PROD) {
            int t = idx >> 5, b = idx & 31;
            unsigned k0, k1;
            threefry(0u, 1u, 0u, (unsigned)t, k0, k1);
            unsigned o0, o1;
            threefry(k0, k1, 0u, (unsigned)(b * 1024 + tid), o0, o1);
            unsigned bits = o0 ^ o1;
            float u = __uint_as_float(0x3f800000u | (bits >> 9)) - 1.0f;
            float r = __ldg(image + b * 1024 + tid) * 0.1953125f;
            sm[PM_XF + tid] = (r > u) ? 1.f : 0.f;
            __syncthreads();

            if (tid < 672) {
                const float* wr = sm + PM_W1 + c1_c * 25;
                float acc[7];
#pragma unroll
                for (int o = 0; o < 7; o++) acc[o] = 0.f;
#pragma unroll
                for (int ky = 0; ky < 5; ky++) {
                    const float* row = sm + PM_XF + (c1_oy + ky) * 32 + c1_x0;
                    float in[11];
#pragma unroll
                    for (int q = 0; q < 11; q++) in[q] = row[q];
#pragma unroll
                    for (int kx = 0; kx < 5; kx++) {
                        float wv = wr[ky * 5 + kx];
#pragma unroll
                        for (int o = 0; o < 7; o++)
                            acc[o] = fmaf(wv, in[kx + o], acc[o]);
                    }
                }
                float* outp = g_drive1 + (size_t)idx * 4704
                            + c1_c * 784 + c1_oy * 28 + c1_x0;
#pragma unroll
                for (int o = 0; o < 7; o++) outp[o] = acc[o];
            }
            __syncthreads();
            if (tid == 0) {
                __threadfence();
                ((volatile int*)g_ready)[idx] = 1;
            }
        }
        return;
    }

    // ================= SIM CTA (one per batch element) =================
    int* const wcnt  = (int*)(sm + SM_WCNT);
    int* const listi = (int*)(sm + SM_LIST);
    const int b = blockIdx.x;

    for (int i = tid; i < 2400; i += 1024) {
        float f = w2[i];
        sm[SM_W2D + 2 * i] = f; sm[SM_W2D + 2 * i + 1] = f;
    }
    for (int i = tid; i < 10080; i += 1024) sm[SM_FW1 + i] = fw1[i];
    for (int i = tid; i < 840;   i += 1024) sm[SM_FW2 + i] = fw2[i];
    for (int i = tid; i < (SM_ZEND - SM_ZBEG); i += 1024) sm[SM_ZBEG + i] = 0.0f;
    if (tid == 0) {
        while (((volatile int*)g_ready)[b] == 0) __nanosleep(64);
    }
    __syncthreads();
    __threadfence();
    {
        const float4* src = (const float4*)(g_drive1 + (size_t)b * 4704);
        float4* dst = (float4*)(sm + SM_DRV);
        for (int i = tid; i < 1176; i += 1024) dst[i] = src[i];
    }
    __syncthreads();

    // ---- static mappings ----
    const int a_c  = tid / 98;                 // A: tid<588 (c, by, p)
    const int a_r  = tid % 98;
    const int a_by = a_r / 7;
    const int a_p  = a_r % 7;
    const int c2_g   = tid >> 4;               // B1: tid<480, g=(ic*5+oy2), lane16=oc
    const int c2_oc  = tid & 15;
    const int c2_ic  = c2_g / 5;
    const int c2_oy2 = c2_g % 5;
    const int c_sp = tid >> 6;                 // C1: tid<512, 8 splits x 64 lanes
    const int c_o2 = tid & 63;
    const int d_g  = tid >> 3;                 // D: tid<672
    const int d_j  = tid & 7;

    // register-resident LIF state
    float pm1[2] = {0.f, 0.f}, pm2[2] = {0.f, 0.f};       // layer2 pooled
    float qm1 = 0.f, qm2 = 0.f;                            // layer4 pooled
    float em1a = 0.f, em2a = 0.f, em1b = 0.f, em2b = 0.f;  // layer5

#pragma unroll 1
    for (int t = 0; t < T_STEPS; t++) {
        // ---- A': lif1(drive from smem) + pool + lif2 -> SKB + SKBO shadow ----
        if (tid < 588) {
            const float* dp = sm + SM_DRV + (t & 1) * 4704
                            + a_c * 784 + (2 * a_by) * 28 + 4 * a_p;
            float4 v0 = *(const float4*)dp;
            float4 v1 = *(const float4*)(dp + 28);
            float acc[8] = {v0.x, v0.y, v0.z, v0.w, v1.x, v1.y, v1.z, v1.w};
            int ob = a_c * 784 + (2 * a_by) * 28 + 4 * a_p;
            float ps[2] = {0.f, 0.f};
#pragma unroll
            for (int q = 0; q < 8; q++) {
                int oy = q >> 2, j = q & 3;
                int o = ob + oy * 28 + j;
                float2 m = *(float2*)(sm + SM_M12A + 2 * o);
                float oms = (m.y > 0.3f) ? 0.f : 1.f;
                float n1 = m.x * 0.25f * oms + acc[q];
                float n2 = m.y * 0.25f * oms + 0.5f * n1;
                *(float2*)(sm + SM_M12A + 2 * o) = make_float2(n1, n2);
                ps[j >> 1] += (n2 > 0.3f) ? 1.f : 0.f;
            }
#pragma unroll
            for (int h = 0; h < 2; h++) {
                float d   = 0.25f * ps[h];
                float oms = (pm2[h] > 0.3f) ? 0.f : 1.f;
                float n1  = pm1[h] * 0.25f * oms + d;
                float n2  = pm2[h] * 0.25f * oms + 0.5f * n1;
                pm1[h] = n1; pm2[h] = n2;
                float sv = (n2 > 0.3f) ? 1.f : 0.f;
                int px = 2 * a_p + h;
                int si = a_c * 196 + a_by * 14 + px;
                sm[SM_SKB + si] = sv;
                if (px > 0) sm[SM_SKBO + si - 1] = sv;
            }
        }
        __syncthreads();

        // ---- B1: conv2 partials f32x2 (broadcast inputs) | drive prefetch ----
        if (tid < 480) {
            const u64* wd = (const u64*)(sm + SM_W2D) + (c2_oc * 6 + c2_ic) * 25;
            const float* re0 = sm + SM_SKB  + c2_ic * 196;
            const float* ro0 = sm + SM_SKBO + c2_ic * 196;
            u64 acc[10];
#pragma unroll
            for (int q = 0; q < 10; q++) acc[q] = 0ull;
#pragma unroll
            for (int r = 0; r < 6; r++) {
                const float* re = re0 + (2 * c2_oy2 + r) * 14;
                const float* ro = ro0 + (2 * c2_oy2 + r) * 14;
                u64 p[13];
#pragma unroll
                for (int k = 0; k < 7; k++) p[2 * k] = *(const u64*)(re + 2 * k);
#pragma unroll
                for (int k = 0; k < 6; k++) p[2 * k + 1] = *(const u64*)(ro + 2 * k);
                if (r < 5) {
#pragma unroll
                    for (int kx = 0; kx < 5; kx++) {
                        u64 w = wd[r * 5 + kx];
#pragma unroll
                        for (int m = 0; m < 5; m++)
                            fma2(acc[m], w, p[kx + 2 * m]);
                    }
                }
                if (r >= 1) {
#pragma unroll
                    for (int kx = 0; kx < 5; kx++) {
                        u64 w = wd[(r - 1) * 5 + kx];
#pragma unroll
                        for (int m = 0; m < 5; m++)
                            fma2(acc[5 + m], w, p[kx + 2 * m]);
                    }
                }
            }
            u64* pp = (u64*)(sm + SM_PARTB + c2_ic * 1600 + c2_oc * 100 + (2 * c2_oy2) * 10);
#pragma unroll
            for (int q = 0; q < 10; q++) pp[q] = acc[q];
        } else if (t + 1 < T_STEPS) {
            int idx = (t + 1) * 32 + b;
            if (lane == 0) {
                while (((volatile int*)g_ready)[idx] == 0) __nanosleep(64);
            }
            __syncwarp();
            __threadfence();
            const float4* src = (const float4*)(g_drive1 + (size_t)idx * 4704);
            float4* dst = (float4*)(sm + SM_DRV + ((t + 1) & 1) * 4704);
            for (int i = tid - 480; i < 1176; i += 544) dst[i] = src[i];
        }
        __syncthreads();

        // ---- B2: reduce ic + lif3 + pool + lif4 + per-warp spike segments ----
        bool spiked = false;
        int myk = 0;
        if (tid < 400) {
            int oc = tid / 25, rem = tid % 25, py = rem / 5, px = rem % 5;
            float s00 = 0.f, s01 = 0.f, s10 = 0.f, s11 = 0.f;
#pragma unroll
            for (int ic = 0; ic < 6; ic++) {
                const float* pb = sm + SM_PARTB + ic * 1600 + oc * 100;
                float2 va = *(const float2*)(pb + (2 * py) * 10 + 2 * px);
                float2 vb = *(const float2*)(pb + (2 * py + 1) * 10 + 2 * px);
                s00 += va.x; s01 += va.y; s10 += vb.x; s11 += vb.y;
            }
            float dr0[4] = {s00, s01, s10, s11};
            float psum = 0.f;
            int ob = oc * 100 + (2 * py) * 10 + 2 * px;
#pragma unroll
            for (int q = 0; q < 4; q++) {
                int o = ob + (q >> 1) * 10 + (q & 1);
                float2 m = *(float2*)(sm + SM_M12C + 2 * o);
                float oms = (m.y > 0.3f) ? 0.f : 1.f;
                float n1 = m.x * 0.25f * oms + dr0[q];
                float n2 = m.y * 0.25f * oms + 0.5f * n1;
                *(float2*)(sm + SM_M12C + 2 * o) = make_float2(n1, n2);
                psum += (n2 > 0.3f) ? 1.f : 0.f;
            }
            float d   = 0.25f * psum;
            float oms = (qm2 > 0.3f) ? 0.f : 1.f;
            float n1  = qm1 * 0.25f * oms + d;
            float n2  = qm2 * 0.25f * oms + 0.5f * n1;
            qm1 = n1; qm2 = n2;
            if (n2 > 0.3f) { spiked = true; myk = tid; }
        }
        {
            unsigned bm = __ballot_sync(0xffffffffu, spiked);
            if (spiked) listi[wrp * 32 + __popc(bm & ((1u << lane) - 1u))] = myk;
            if (lane == 0 && wrp < 13) wcnt[wrp] = __popc(bm);
        }
        __syncthreads();

        // ---- C1: sparse conv3 gather (u64 pairs), 8-way segment split ----
        u64 cacc = 0ull;
        if (tid < 512 && c_o2 < 60) {
            const u64* w3p = (const u64*)g_w3t;
            for (int w = c_sp; w < 13; w += 8) {
                int n = wcnt[w];
                const int* seg = listi + w * 32;
                for (int j = 0; j < n; j++) {
                    int k = seg[j];
                    add2(cacc, __ldg(w3p + k * 60 + c_o2));
                }
            }
            if (c_sp) *(u64*)(sm + SM_PARTC + (c_sp - 1) * 120 + 2 * c_o2) = cacc;
        }
        __syncthreads();

        // ---- C2: combine + lif5 -> SKE ----
        if (tid < 60) {
#pragma unroll
            for (int s7 = 0; s7 < 7; s7++)
                add2(cacc, *(const u64*)(sm + SM_PARTC + s7 * 120 + 2 * tid));
            float2 v = u2f(cacc);
            float oms = (em2a > 0.3f) ? 0.f : 1.f;
            float n1  = em1a * 0.25f * oms + v.x;
            float n2  = em2a * 0.25f * oms + 0.5f * n1;
            em1a = n1; em2a = n2;
            sm[SM_SKE + 2 * tid] = (n2 > 0.3f) ? 1.f : 0.f;
            float omsb = (em2b > 0.3f) ? 0.f : 1.f;
            float n1b  = em1b * 0.25f * omsb + v.y;
            float n2b  = em2b * 0.25f * omsb + 0.5f * n1b;
            em1b = n1b; em2b = n2b;
            sm[SM_SKE + 2 * tid + 1] = (n2b > 0.3f) ? 1.f : 0.f;
        }
        __syncthreads();

        // ---- D: fc1 + lif6 -> SKF ----
        if (tid < 672) {
            const float* wp = sm + SM_FW1 + d_g * 120;
            float s = 0.f;
#pragma unroll
            for (int k = d_j; k < 120; k += 8) s = fmaf(wp[k], sm[SM_SKE + k], s);
            s += __shfl_xor_sync(0xffffffffu, s, 4);
            s += __shfl_xor_sync(0xffffffffu, s, 2);
            s += __shfl_xor_sync(0xffffffffu, s, 1);
            if (d_j == 0) {
                float2 m = *(float2*)(sm + SM_M12F + 2 * d_g);
                float oms = (m.y > 0.3f) ? 0.f : 1.f;
                float n1 = m.x * 0.25f * oms + s;
                float n2 = m.y * 0.25f * oms + 0.5f * n1;
                *(float2*)(sm + SM_M12F + 2 * d_g) = make_float2(n1, n2);
                sm[SM_SKF + d_g] = (n2 > 0.3f) ? 1.f : 0.f;
            }
        }
        __syncthreads();

        // ---- E: fc2 + lif7 + acc (warps 0-9) ----
        if (wrp < 10) {
            const float* wp = sm + SM_FW2 + wrp * 84;
            float s = 0.f;
            for (int k = lane; k < 84; k += 32) s = fmaf(wp[k], sm[SM_SKF + k], s);
#pragma unroll
            for (int d2 = 16; d2 > 0; d2 >>= 1) s += __shfl_xor_sync(0xffffffffu, s, d2);
            if (lane == 0) {
                float2 m = *(float2*)(sm + SM_M12G + 2 * wrp);
                float oms = (m.y > 0.3f) ? 0.f : 1.f;
                float n1 = m.x * 0.25f * oms + s;
                float n2 = m.y * 0.25f * oms + 0.5f * n1;
                *(float2*)(sm + SM_M12G + 2 * wrp) = make_float2(n1, n2);
                sm[SM_ACC + wrp] += (n2 > 0.3f) ? 1.f : 0.f;
            }
        }
        __syncthreads();
    }

    if (tid < 10)
        out[b * 10 + tid] = sm[SM_ACC + tid] * (1.0f / 512.0f);
}

extern "C" void kernel_launch(void* const* d_in, const int* in_sizes, int n_in,
                              void* d_out, int out_size)
{
    const float* image = (const float*)d_in[0];
    const float* w1    = (const float*)d_in[1];
    const float* w2    = (const float*)d_in[2];
    const float* w3    = (const float*)d_in[3];
    const float* fw1   = (const float*)d_in[4];
    const float* fw2   = (const float*)d_in[5];
    float* out = (float*)d_out;

    reset_kernel<<<(N_TILES + 1023) / 1024, 1024>>>();
    w3t_kernel<<<(48000 + 255) / 256, 256>>>(w3);
    cudaFuncSetAttribute(fused_kernel, cudaFuncAttributeMaxDynamicSharedMemorySize, SMEM_BYTES);
    fused_kernel<<<N_SIM + N_PROD, 1024, SMEM_BYTES>>>(image, w1, w2, fw1, fw2, out);
}

// round 14
// speedup vs baseline: 2.0719x; 1.0076x over previous
#include <cuda_runtime.h>
#include <cstdint>

#define T_STEPS 512
#define N_SIM   32
#define N_PROD  116
#define N_TILES (T_STEPS * 32)

__device__ __align__(8) float g_w3t[401 * 120];       // conv3 weights [k][o]; row 400 = zeros
__device__ float g_drive1[(size_t)N_TILES * 4704];    // conv1 drive [t][b][4704]
__device__ int   g_ready[N_TILES];

// ---------------- threefry2x32 (JAX), 20 rounds ----------------
__device__ __forceinline__ void threefry(unsigned k0, unsigned k1,
                                         unsigned x0, unsigned x1,
                                         unsigned &o0, unsigned &o1)
{
    unsigned k2 = k0 ^ k1 ^ 0x1BD11BDAu;
    x0 += k0; x1 += k1;
#define TF_R(r) { x0 += x1; x1 = __funnelshift_l(x1, x1, (r)); x1 ^= x0; }
    TF_R(13) TF_R(15) TF_R(26) TF_R(6)
    x0 += k1; x1 += k2 + 1u;
    TF_R(17) TF_R(29) TF_R(16) TF_R(24)
    x0 += k2; x1 += k0 + 2u;
    TF_R(13) TF_R(15) TF_R(26) TF_R(6)
    x0 += k0; x1 += k1 + 3u;
    TF_R(17) TF_R(29) TF_R(16) TF_R(24)
    x0 += k1; x1 += k2 + 4u;
    TF_R(13) TF_R(15) TF_R(26) TF_R(6)
    x0 += k2; x1 += k0 + 5u;
#undef TF_R
    o0 = x0; o1 = x1;
}

__global__ void __launch_bounds__(1024) reset_kernel()
{
    int i = blockIdx.x * 1024 + threadIdx.x;
    if (i < N_TILES) g_ready[i] = 0;
}

__global__ void __launch_bounds__(256) w3t_kernel(const float* __restrict__ w3)
{
    int i = blockIdx.x * 256 + threadIdx.x;   // 48120 (row 400 forced to 0)
    if (i < 48000) {
        int k = i / 120, o = i % 120;
        g_w3t[i] = w3[o * 400 + k];
    } else if (i < 48120) {
        g_w3t[i] = 0.0f;                      // sentinel row (replay-safe)
    }
}

typedef unsigned long long u64;
__device__ __forceinline__ void add2(u64 &acc, u64 p)
{
    asm("add.rn.f32x2 %0, %1, %2;" : "=l"(acc) : "l"(p), "l"(acc));
}
__device__ __forceinline__ float2 u2f(u64 v)
{
    float2 r;
    asm("mov.b64 {%0, %1}, %2;" : "=f"(r.x), "=f"(r.y) : "l"(v));
    return r;
}

// ---------------- shared memory map (float offsets) ----------------
#define SM_DRV    0        // 9408 = 2 x 4704 drive double buffer
#define SM_SKB    9408     // 1176
#define SM_M12A   10584    // 9408
#define SM_M12C   19992    // 3200
#define SM_PARTB  23192    // 9600 = ic(6) x oc(16) x 10 x 10
#define SM_PARTC  32792    // 840 = 7 x 120
#define SM_SKE    33632    // 120
#define SM_M12F   33752    // 168
#define SM_SKF    33920    // 84
#define SM_M12G   34004    // 20
#define SM_ACC    34024    // 10
#define SM_WCNT   34034    // 13 ints
#define SM_LIST   34048    // 416 ints
#define SM_W2     34464    // 2400
#define SM_FW1    36864    // 10080
#define SM_FW2    46944    // 840
#define SM_TOTAL  47784
#define SMEM_BYTES (SM_TOTAL * 4)
#define SM_ZBEG   SM_SKB
#define SM_ZEND   SM_W2
// producer view of the same smem
#define PM_XF     0
#define PM_W1     1024

__global__ void __launch_bounds__(1024, 1)
fused_kernel(const float* __restrict__ image, const float* __restrict__ w1,
             const float* __restrict__ w2, const float* __restrict__ fw1,
             const float* __restrict__ fw2, float* __restrict__ out)
{
    extern __shared__ float sm[];
    const int tid  = threadIdx.x;
    const int lane = tid & 31;
    const int wrp  = tid >> 5;

    if (blockIdx.x >= N_SIM) {
        // ================= PRODUCER: RNG + conv1 for tiles (t,b) =================
        const int p = blockIdx.x - N_SIM;
        if (tid < 150) sm[PM_W1 + tid] = w1[tid];
        __syncthreads();
        const int c1_c  = tid / 112;           // conv1: tid<672
        const int c1_r  = tid % 112;
        const int c1_oy = c1_r >> 2;
        const int c1_x0 = (c1_r & 3) * 7;

        for (int idx = p; idx < N_TILES; idx += N_PROD) {
            int t = idx >> 5, b = idx & 31;
            unsigned k0, k1;
            threefry(0u, 1u, 0u, (unsigned)t, k0, k1);
            unsigned o0, o1;
            threefry(k0, k1, 0u, (unsigned)(b * 1024 + tid), o0, o1);
            unsigned bits = o0 ^ o1;
            float u = __uint_as_float(0x3f800000u | (bits >> 9)) - 1.0f;
            float r = __ldg(image + b * 1024 + tid) * 0.1953125f;
            sm[PM_XF + tid] = (r > u) ? 1.f : 0.f;
            __syncthreads();

            if (tid < 672) {
                const float* wr = sm + PM_W1 + c1_c * 25;
                float acc[7];
#pragma unroll
                for (int o = 0; o < 7; o++) acc[o] = 0.f;
#pragma unroll
                for (int ky = 0; ky < 5; ky++) {
                    const float* row = sm + PM_XF + (c1_oy + ky) * 32 + c1_x0;
                    float in[11];
#pragma unroll
                    for (int q = 0; q < 11; q++) in[q] = row[q];
#pragma unroll
                    for (int kx = 0; kx < 5; kx++) {
                        float wv = wr[ky * 5 + kx];
#pragma unroll
                        for (int o = 0; o < 7; o++)
                            acc[o] = fmaf(wv, in[kx + o], acc[o]);
                    }
                }
                float* outp = g_drive1 + (size_t)idx * 4704
                            + c1_c * 784 + c1_oy * 28 + c1_x0;
#pragma unroll
                for (int o = 0; o < 7; o++) outp[o] = acc[o];
            }
            __syncthreads();
            if (tid == 0) {
                __threadfence();
                ((volatile int*)g_ready)[idx] = 1;
            }
        }
        return;
    }

    // ================= SIM CTA (one per batch element) =================
    int* const wcnt  = (int*)(sm + SM_WCNT);
    int* const listi = (int*)(sm + SM_LIST);
    const int b = blockIdx.x;

    for (int i = tid; i < 2400;  i += 1024) sm[SM_W2  + i] = w2[i];
    for (int i = tid; i < 10080; i += 1024) sm[SM_FW1 + i] = fw1[i];
    for (int i = tid; i < 840;   i += 1024) sm[SM_FW2 + i] = fw2[i];
    for (int i = tid; i < (SM_ZEND - SM_ZBEG); i += 1024) sm[SM_ZBEG + i] = 0.0f;
    if (tid == 0) {
        while (((volatile int*)g_ready)[b] == 0) __nanosleep(64);
    }
    __syncthreads();
    __threadfence();
    {
        const float4* src = (const float4*)(g_drive1 + (size_t)b * 4704);
        float4* dst = (float4*)(sm + SM_DRV);
        for (int i = tid; i < 1176; i += 1024) dst[i] = src[i];
    }
    __syncthreads();

    // ---- static mappings ----
    const int a_l  = tid - 320;                // A: tids [320, 908) (c, by, p)
    const int a_c  = a_l / 98;
    const int a_r  = a_l % 98;
    const int a_by = a_r / 7;
    const int a_p  = a_r % 7;
    const int c2_g   = tid >> 4;               // B1: tid<480, g=(ic*5+oy2), lane16=oc
    const int c2_oc  = tid & 15;
    const int c2_ic  = c2_g / 5;
    const int c2_oy2 = c2_g % 5;
    const int c_sp = tid >> 6;                 // C1: tid<512, 8 splits x 64 lanes
    const int c_o2 = tid & 63;
    const int d_g  = tid >> 3;                 // D: tid<672
    const int d_j  = tid & 7;

    // register-resident LIF state
    float pm1[2] = {0.f, 0.f}, pm2[2] = {0.f, 0.f};       // layer2 pooled (A warps)
    float qm1 = 0.f, qm2 = 0.f;                            // layer4 pooled (B2 warps)
    float em1a = 0.f, em2a = 0.f, em1b = 0.f, em2b = 0.f;  // layer5 (C2 threads)

#pragma unroll 1
    for (int t = 0; t < T_STEPS; t++) {
        // ---- A(t) on tids 320..907  ||  E(t-1) on warps 0..9 ----
        if (tid >= 320 && tid < 908) {
            const float* dp = sm + SM_DRV + (t & 1) * 4704
                            + a_c * 784 + (2 * a_by) * 28 + 4 * a_p;
            float4 v0 = *(const float4*)dp;
            float4 v1 = *(const float4*)(dp + 28);
            float acc[8] = {v0.x, v0.y, v0.z, v0.w, v1.x, v1.y, v1.z, v1.w};
            int ob = a_c * 784 + (2 * a_by) * 28 + 4 * a_p;
            float ps[2] = {0.f, 0.f};
#pragma unroll
            for (int q = 0; q < 8; q++) {
                int oy = q >> 2, j = q & 3;
                int o = ob + oy * 28 + j;
                float2 m = *(float2*)(sm + SM_M12A + 2 * o);
                float oms = (m.y > 0.3f) ? 0.f : 1.f;
                float n1 = m.x * 0.25f * oms + acc[q];
                float n2 = m.y * 0.25f * oms + 0.5f * n1;
                *(float2*)(sm + SM_M12A + 2 * o) = make_float2(n1, n2);
                ps[j >> 1] += (n2 > 0.3f) ? 1.f : 0.f;
            }
#pragma unroll
            for (int h = 0; h < 2; h++) {
                float d   = 0.25f * ps[h];
                float oms = (pm2[h] > 0.3f) ? 0.f : 1.f;
                float n1  = pm1[h] * 0.25f * oms + d;
                float n2  = pm2[h] * 0.25f * oms + 0.5f * n1;
                pm1[h] = n1; pm2[h] = n2;
                sm[SM_SKB + a_c * 196 + a_by * 14 + 2 * a_p + h] = (n2 > 0.3f) ? 1.f : 0.f;
            }
        } else if (wrp < 10 && t > 0) {
            // E(t-1): fc2 + lif7 + acc
            const float* wp = sm + SM_FW2 + wrp * 84;
            float s = 0.f;
            for (int k = lane; k < 84; k += 32) s = fmaf(wp[k], sm[SM_SKF + k], s);
#pragma unroll
            for (int d2 = 16; d2 > 0; d2 >>= 1) s += __shfl_xor_sync(0xffffffffu, s, d2);
            if (lane == 0) {
                float2 m = *(float2*)(sm + SM_M12G + 2 * wrp);
                float oms = (m.y > 0.3f) ? 0.f : 1.f;
                float n1 = m.x * 0.25f * oms + s;
                float n2 = m.y * 0.25f * oms + 0.5f * n1;
                *(float2*)(sm + SM_M12G + 2 * wrp) = make_float2(n1, n2);
                sm[SM_ACC + wrp] += (n2 > 0.3f) ? 1.f : 0.f;
            }
        }
        __syncthreads();

        // ---- B1: conv2 partials (lane16=oc broadcast) | drive prefetch ----
        if (tid < 480) {
            const float* wr = sm + SM_W2 + (c2_oc * 6 + c2_ic) * 25;
            const float* ib = sm + SM_SKB + c2_ic * 196;
            float acc[20];
#pragma unroll
            for (int q = 0; q < 20; q++) acc[q] = 0.f;
#pragma unroll
            for (int r = 0; r < 6; r++) {
                const float2* rp = (const float2*)(ib + (2 * c2_oy2 + r) * 14);
                float in[14];
#pragma unroll
                for (int k = 0; k < 7; k++) {
                    float2 v = rp[k];
                    in[2 * k] = v.x; in[2 * k + 1] = v.y;
                }
                if (r < 5) {
#pragma unroll
                    for (int kx = 0; kx < 5; kx++) {
                        float wv = wr[r * 5 + kx];
#pragma unroll
                        for (int ox = 0; ox < 10; ox++)
                            acc[ox] = fmaf(wv, in[kx + ox], acc[ox]);
                    }
                }
                if (r >= 1) {
#pragma unroll
                    for (int kx = 0; kx < 5; kx++) {
                        float wv = wr[(r - 1) * 5 + kx];
#pragma unroll
                        for (int ox = 0; ox < 10; ox++)
                            acc[10 + ox] = fmaf(wv, in[kx + ox], acc[10 + ox]);
                    }
                }
            }
            float2* pp = (float2*)(sm + SM_PARTB + c2_ic * 1600 + c2_oc * 100 + (2 * c2_oy2) * 10);
#pragma unroll
            for (int q = 0; q < 10; q++)
                pp[q] = make_float2(acc[2 * q], acc[2 * q + 1]);
        } else if (t + 1 < T_STEPS) {
            int idx = (t + 1) * 32 + b;
            if (lane == 0) {
                while (((volatile int*)g_ready)[idx] == 0) __nanosleep(64);
            }
            __syncwarp();
            __threadfence();
            const float4* src = (const float4*)(g_drive1 + (size_t)idx * 4704);
            float4* dst = (float4*)(sm + SM_DRV + ((t + 1) & 1) * 4704);
            for (int i = tid - 480; i < 1176; i += 544) dst[i] = src[i];
        }
        __syncthreads();

        // ---- B2: reduce ic + lif3 + pool + lif4 + padded spike segments ----
        bool spiked = false;
        int myk = 0;
        if (tid < 400) {
            int oc = tid / 25, rem = tid % 25, py = rem / 5, px = rem % 5;
            float s00 = 0.f, s01 = 0.f, s10 = 0.f, s11 = 0.f;
#pragma unroll
            for (int ic = 0; ic < 6; ic++) {
                const float* pb = sm + SM_PARTB + ic * 1600 + oc * 100;
                float2 va = *(const float2*)(pb + (2 * py) * 10 + 2 * px);
                float2 vb = *(const float2*)(pb + (2 * py + 1) * 10 + 2 * px);
                s00 += va.x; s01 += va.y; s10 += vb.x; s11 += vb.y;
            }
            float dr0[4] = {s00, s01, s10, s11};
            float psum = 0.f;
            int ob = oc * 100 + (2 * py) * 10 + 2 * px;
#pragma unroll
            for (int q = 0; q < 4; q++) {
                int o = ob + (q >> 1) * 10 + (q & 1);
                float2 m = *(float2*)(sm + SM_M12C + 2 * o);
                float oms = (m.y > 0.3f) ? 0.f : 1.f;
                float n1 = m.x * 0.25f * oms + dr0[q];
                float n2 = m.y * 0.25f * oms + 0.5f * n1;
                *(float2*)(sm + SM_M12C + 2 * o) = make_float2(n1, n2);
                psum += (n2 > 0.3f) ? 1.f : 0.f;
            }
            float d   = 0.25f * psum;
            float oms = (qm2 > 0.3f) ? 0.f : 1.f;
            float n1  = qm1 * 0.25f * oms + d;
            float n2  = qm2 * 0.25f * oms + 0.5f * n1;
            qm1 = n1; qm2 = n2;
            if (n2 > 0.3f) { spiked = true; myk = tid; }
        }
        if (wrp < 13) {
            unsigned bm = __ballot_sync(0xffffffffu, spiked);
            int cnt = __popc(bm);
            if (spiked) listi[wrp * 32 + __popc(bm & ((1u << lane) - 1u))] = myk;
            if (lane == cnt) listi[wrp * 32 + lane] = 400;   // sentinel pad (zero row)
            if (lane == 0) wcnt[wrp] = cnt;
        }
        __syncthreads();

        // ---- C1: sparse conv3 gather, unroll-2 via sentinel pad ----
        u64 cacc = 0ull;
        if (tid < 512 && c_o2 < 60) {
            const u64* w3p = (const u64*)g_w3t;
            for (int w = c_sp; w < 13; w += 8) {
                int n = wcnt[w];
                const int* seg = listi + w * 32;
                for (int j = 0; j < n; j += 2) {
                    int k0 = seg[j];
                    int k1 = seg[j + 1];          // may be sentinel 400 (zero row)
                    u64 v0 = __ldg(w3p + k0 * 60 + c_o2);
                    u64 v1 = __ldg(w3p + k1 * 60 + c_o2);
                    add2(cacc, v0);
                    add2(cacc, v1);
                }
            }
            if (c_sp) *(u64*)(sm + SM_PARTC + (c_sp - 1) * 120 + 2 * c_o2) = cacc;
        }
        __syncthreads();

        // ---- C2: combine + lif5 -> SKE ----
        if (tid < 60) {
#pragma unroll
            for (int s7 = 0; s7 < 7; s7++)
                add2(cacc, *(const u64*)(sm + SM_PARTC + s7 * 120 + 2 * tid));
            float2 v = u2f(cacc);
            float oms = (em2a > 0.3f) ? 0.f : 1.f;
            float n1  = em1a * 0.25f * oms + v.x;
            float n2  = em2a * 0.25f * oms + 0.5f * n1;
            em1a = n1; em2a = n2;
            sm[SM_SKE + 2 * tid] = (n2 > 0.3f) ? 1.f : 0.f;
            float omsb = (em2b > 0.3f) ? 0.f : 1.f;
            float n1b  = em1b * 0.25f * omsb + v.y;
            float n2b  = em2b * 0.25f * omsb + 0.5f * n1b;
            em1b = n1b; em2b = n2b;
            sm[SM_SKE + 2 * tid + 1] = (n2b > 0.3f) ? 1.f : 0.f;
        }
        __syncthreads();

        // ---- D: fc1 + lif6 -> SKF ----
        if (tid < 672) {
            const float* wp = sm + SM_FW1 + d_g * 120;
            float s = 0.f;
#pragma unroll
            for (int k = d_j; k < 120; k += 8) s = fmaf(wp[k], sm[SM_SKE + k], s);
            s += __shfl_xor_sync(0xffffffffu, s, 4);
            s += __shfl_xor_sync(0xffffffffu, s, 2);
            s += __shfl_xor_sync(0xffffffffu, s, 1);
            if (d_j == 0) {
                float2 m = *(float2*)(sm + SM_M12F + 2 * d_g);
                float oms = (m.y > 0.3f) ? 0.f : 1.f;
                float n1 = m.x * 0.25f * oms + s;
                float n2 = m.y * 0.25f * oms + 0.5f * n1;
                *(float2*)(sm + SM_M12F + 2 * d_g) = make_float2(n1, n2);
                sm[SM_SKF + d_g] = (n2 > 0.3f) ? 1.f : 0.f;
            }
        }
        __syncthreads();
    }

    // ---- drain: E(T_STEPS-1) ----
    if (wrp < 10) {
        const float* wp = sm + SM_FW2 + wrp * 84;
        float s = 0.f;
        for (int k = lane; k < 84; k += 32) s = fmaf(wp[k], sm[SM_SKF + k], s);
#pragma unroll
        for (int d2 = 16; d2 > 0; d2 >>= 1) s += __shfl_xor_sync(0xffffffffu, s, d2);
        if (lane == 0) {
            float2 m = *(float2*)(sm + SM_M12G + 2 * wrp);
            float oms = (m.y > 0.3f) ? 0.f : 1.f;
            float n1 = m.x * 0.25f * oms + s;
            float n2 = m.y * 0.25f * oms + 0.5f * n1;
            sm[SM_ACC + wrp] += (n2 > 0.3f) ? 1.f : 0.f;
        }
    }
    __syncthreads();

    if (tid < 10)
        out[b * 10 + tid] = sm[SM_ACC + tid] * (1.0f / 512.0f);
}

extern "C" void kernel_launch(void* const* d_in, const int* in_sizes, int n_in,
                              void* d_out, int out_size)
{
    const float* image = (const float*)d_in[0];
    const float* w1    = (const float*)d_in[1];
    const float* w2    = (const float*)d_in[2];
    const float* w3    = (const float*)d_in[3];
    const float* fw1   = (const float*)d_in[4];
    const float* fw2   = (const float*)d_in[5];
    float* out = (float*)d_out;

    reset_kernel<<<(N_TILES + 1023) / 1024, 1024>>>();
    w3t_kernel<<<(48120 + 255) / 256, 256>>>(w3);
    cudaFuncSetAttribute(fused_kernel, cudaFuncAttributeMaxDynamicSharedMemorySize, SMEM_BYTES);
    fused_kernel<<<N_SIM + N_PROD, 1024, SMEM_BYTES>>>(image, w1, w2, fw1, fw2, out);
}